// round 12
// baseline (speedup 1.0000x reference)
#include <cuda_runtime.h>
#include <cuda_fp16.h>
#include <cstdint>
#include <math.h>

#define N_NODES 40000
#define DIN 512
#define DH 256
#define DOUT 47
#define DP 48            // padded layer-2 width (multiple of 4)
#define MAX_E 640000

// Scratch (no cudaMalloc allowed) — __device__ globals.
__device__ __align__(16) __half g_xh[N_NODES * DIN]; // X in fp16
__device__ __align__(16) __half g_w1t[DH * DIN];     // W1^T in fp16 [n][k]
__device__ __align__(16) __half g_h1h[N_NODES * DH]; // X @ W1 (fp16 storage)
__device__ __align__(16) __half g_h2h[N_NODES * DP]; // relu(agg1) @ W2 (fp16, padded)
__device__ float g_dis[N_NODES];                     // deg^-1/2 (deg includes self-loop)
__device__ int   g_deg[N_NODES];
__device__ int   g_src[MAX_E];
__device__ int   g_dst[MAX_E];
__device__ int   g_off[N_NODES + 1];                 // CSR row offsets (by dst)
__device__ int   g_cursor[N_NODES];                  // fill cursors
__device__ int   g_csr_src[MAX_E];                   // src indices sorted by dst
__device__ int   g_is64;                             // 1 if edge_index is int64

__device__ __forceinline__ void cp16(void* smem_dst, const void* gsrc) {
    uint32_t s = (uint32_t)__cvta_generic_to_shared(smem_dst);
    asm volatile("cp.async.cg.shared.global [%0], [%1], 16;" :: "r"(s), "l"(gsrc));
}

// Load 4 consecutive halfs as 2 float2.
__device__ __forceinline__ void ldh4(const __half* p, float2& lo, float2& hi) {
    uint2 u = *reinterpret_cast<const uint2*>(p);
    lo = __half22float2(*reinterpret_cast<const __half2*>(&u.x));
    hi = __half22float2(*reinterpret_cast<const __half2*>(&u.y));
}

// ---------------------------------------------------------------------------
// Init: zero degrees + dtype flag.
// ---------------------------------------------------------------------------
__global__ void k_init() {
    int i = blockIdx.x * blockDim.x + threadIdx.x;
    if (i < N_NODES) g_deg[i] = 0;
    if (i == 0) g_is64 = 1;
}

__global__ void k_detect(const int* __restrict__ w, int nwords2E) {
    int i = blockIdx.x * blockDim.x + threadIdx.x;
    int odd = 2 * i + 1;
    if (odd < nwords2E && w[odd] != 0) g_is64 = 0;
}

// Extract indices AND count degrees in one pass.
__global__ void k_extract_count(const int* __restrict__ w, int E) {
    int e = blockIdx.x * blockDim.x + threadIdx.x;
    if (e >= E) return;
    int s, d;
    if (g_is64) {
        s = w[2 * e];
        d = w[2 * (E + e)];
    } else {
        s = w[e];
        d = w[E + e];
    }
    g_src[e] = s;
    g_dst[e] = d;
    atomicAdd(&g_deg[d], 1);
}

// ---------------------------------------------------------------------------
// Input conversions to fp16.
// ---------------------------------------------------------------------------
__global__ void __launch_bounds__(256)
k_convX(const float* __restrict__ x) {
    size_t i = ((size_t)blockIdx.x * 256 + threadIdx.x) * 8;
    float4 v0 = *reinterpret_cast<const float4*>(&x[i]);
    float4 v1 = *reinterpret_cast<const float4*>(&x[i + 4]);
    __half2 h[4];
    h[0] = __floats2half2_rn(v0.x, v0.y);
    h[1] = __floats2half2_rn(v0.z, v0.w);
    h[2] = __floats2half2_rn(v1.x, v1.y);
    h[3] = __floats2half2_rn(v1.z, v1.w);
    *reinterpret_cast<uint4*>(&g_xh[i]) = *reinterpret_cast<uint4*>(h);
}

__global__ void __launch_bounds__(256)
k_convW1t(const float* __restrict__ W1) {
    int idx = blockIdx.x * 256 + threadIdx.x;   // over DH*DIN
    if (idx >= DH * DIN) return;
    int n = idx / DIN, k = idx % DIN;
    g_w1t[idx] = __float2half_rn(W1[(size_t)k * DH + n]);
}

// ---------------------------------------------------------------------------
// Prefix scan over g_deg -> g_off + cursors + dis (single block).
// ---------------------------------------------------------------------------
#define SCAN_T 1024
#define SCAN_PER ((N_NODES + SCAN_T - 1) / SCAN_T)   // 40
__global__ void __launch_bounds__(SCAN_T)
k_scan_dis() {
    __shared__ int part[SCAN_T];
    int t = threadIdx.x;
    int base = t * SCAN_PER;
    int sum = 0;
#pragma unroll 4
    for (int i = 0; i < SCAN_PER; i++) {
        int idx = base + i;
        if (idx < N_NODES) sum += g_deg[idx];
    }
    part[t] = sum;
    __syncthreads();
    for (int o = 1; o < SCAN_T; o <<= 1) {
        int v = (t >= o) ? part[t - o] : 0;
        __syncthreads();
        part[t] += v;
        __syncthreads();
    }
    int off = (t == 0) ? 0 : part[t - 1];
    for (int i = 0; i < SCAN_PER; i++) {
        int idx = base + i;
        if (idx < N_NODES) {
            g_off[idx] = off;
            g_cursor[idx] = off;
            off += g_deg[idx];
            g_dis[idx] = rsqrtf((float)g_deg[idx] + 1.0f);  // +1 = self loop
        }
    }
    if (t == SCAN_T - 1) g_off[N_NODES] = off;
}

__global__ void k_fill(int E) {
    int e = blockIdx.x * blockDim.x + threadIdx.x;
    if (e >= E) return;
    int d = g_dst[e];
    int pos = atomicAdd(&g_cursor[d], 1);
    g_csr_src[pos] = g_src[e];
}

// ---------------------------------------------------------------------------
// fp16 MMA m16n8k16
// ---------------------------------------------------------------------------
__device__ __forceinline__ void mma_f16(float* c, const uint32_t* a, const uint32_t* b) {
    asm volatile(
        "mma.sync.aligned.m16n8k16.row.col.f32.f16.f16.f32 "
        "{%0,%1,%2,%3}, {%4,%5,%6,%7}, {%8,%9}, {%0,%1,%2,%3};"
        : "+f"(c[0]), "+f"(c[1]), "+f"(c[2]), "+f"(c[3])
        : "r"(a[0]), "r"(a[1]), "r"(a[2]), "r"(a[3]),
          "r"(b[0]), "r"(b[1]));
}

// ---------------------------------------------------------------------------
// GEMM1 (fp16 tensor cores, cp.async double-buffered):
//   h1 = X[40000,512] @ W1[512,256], fp16 in / fp32 accum / fp16 out.
// Block 128x128, 256 threads, 8 warps (4x2), warp tile 32x64, BK=32.
// ---------------------------------------------------------------------------
#define BKH 32
#define NKTH (DIN / BKH)   // 16
__global__ void __launch_bounds__(256, 2)
k_gemm1h() {
    __shared__ __half As[2][128][BKH + 8];
    __shared__ __half Bs[2][128][BKH + 8];

    const int tid = threadIdx.x;
    const int warp = tid >> 5, lane = tid & 31;
    const int gid = lane >> 2, tig = lane & 3;
    const int warpRow = warp >> 1, warpCol = warp & 1;
    const int bm = blockIdx.y * 128;
    const int bn = blockIdx.x * 128;

    const int r0 = tid >> 2,          c0 = (tid & 3) * 8;
    const int r1 = (tid + 256) >> 2,  c1 = c0;
    const int ag0 = (bm + r0 < N_NODES) ? bm + r0 : N_NODES - 1;
    const int ag1 = (bm + r1 < N_NODES) ? bm + r1 : N_NODES - 1;

    float acc[2][8][4];
#pragma unroll
    for (int mi = 0; mi < 2; mi++)
#pragma unroll
        for (int ni = 0; ni < 8; ni++)
#pragma unroll
            for (int r = 0; r < 4; r++) acc[mi][ni][r] = 0.0f;

    {
        cp16(&As[0][r0][c0], &g_xh[(size_t)ag0 * DIN + c0]);
        cp16(&As[0][r1][c1], &g_xh[(size_t)ag1 * DIN + c1]);
        cp16(&Bs[0][r0][c0], &g_w1t[(size_t)(bn + r0) * DIN + c0]);
        cp16(&Bs[0][r1][c1], &g_w1t[(size_t)(bn + r1) * DIN + c1]);
        asm volatile("cp.async.commit_group;");
    }

    int buf = 0;
    for (int kt = 0; kt < NKTH; kt++) {
        if (kt + 1 < NKTH) {
            int k0 = (kt + 1) * BKH;
            int nb = buf ^ 1;
            cp16(&As[nb][r0][c0], &g_xh[(size_t)ag0 * DIN + k0 + c0]);
            cp16(&As[nb][r1][c1], &g_xh[(size_t)ag1 * DIN + k0 + c1]);
            cp16(&Bs[nb][r0][c0], &g_w1t[(size_t)(bn + r0) * DIN + k0 + c0]);
            cp16(&Bs[nb][r1][c1], &g_w1t[(size_t)(bn + r1) * DIN + k0 + c1]);
            asm volatile("cp.async.commit_group;");
            asm volatile("cp.async.wait_group 1;");
        } else {
            asm volatile("cp.async.wait_group 0;");
        }
        __syncthreads();

#pragma unroll
        for (int kk = 0; kk < 2; kk++) {
            int kb = kk * 16 + tig * 2;
            uint32_t a[2][4], b[8][2];
#pragma unroll
            for (int mi = 0; mi < 2; mi++) {
                int r = warpRow * 32 + mi * 16 + gid;
                a[mi][0] = *reinterpret_cast<const uint32_t*>(&As[buf][r][kb]);
                a[mi][1] = *reinterpret_cast<const uint32_t*>(&As[buf][r + 8][kb]);
                a[mi][2] = *reinterpret_cast<const uint32_t*>(&As[buf][r][kb + 8]);
                a[mi][3] = *reinterpret_cast<const uint32_t*>(&As[buf][r + 8][kb + 8]);
            }
#pragma unroll
            for (int ni = 0; ni < 8; ni++) {
                int c = warpCol * 64 + ni * 8 + gid;
                b[ni][0] = *reinterpret_cast<const uint32_t*>(&Bs[buf][c][kb]);
                b[ni][1] = *reinterpret_cast<const uint32_t*>(&Bs[buf][c][kb + 8]);
            }
#pragma unroll
            for (int mi = 0; mi < 2; mi++)
#pragma unroll
                for (int ni = 0; ni < 8; ni++)
                    mma_f16(acc[mi][ni], a[mi], b[ni]);
        }
        __syncthreads();
        buf ^= 1;
    }

#pragma unroll
    for (int mi = 0; mi < 2; mi++) {
        int row0 = bm + warpRow * 32 + mi * 16 + gid;
        int row1 = row0 + 8;
#pragma unroll
        for (int ni = 0; ni < 8; ni++) {
            int col = bn + warpCol * 64 + ni * 8 + tig * 2;
            if (row0 < N_NODES)
                *reinterpret_cast<__half2*>(&g_h1h[(size_t)row0 * DH + col]) =
                    __floats2half2_rn(acc[mi][ni][0], acc[mi][ni][1]);
            if (row1 < N_NODES)
                *reinterpret_cast<__half2*>(&g_h1h[(size_t)row1 * DH + col]) =
                    __floats2half2_rn(acc[mi][ni][2], acc[mi][ni][3]);
        }
    }
}

// ---------------------------------------------------------------------------
// FUSED layer-1 aggregation + relu + GEMM2:
//   o1row = b1 + dis[d]^2*h1[d] + sum_s nrm*h1[s]    (gather, regs)
//   h2[d] = relu(o1row) @ W2                         (SMEM-staged, in-block)
// Block (64,4): 4 nodes per block. Phase 1: lane = 4-feature chunk of 256.
// Phase 2: lane = output column (47 of 64 active), SMEM broadcast reads.
// ---------------------------------------------------------------------------
__global__ void __launch_bounds__(256)
k_agg1f(const float* __restrict__ b1, const float* __restrict__ W2) {
    __shared__ float s_h[4][DH];
    int y = threadIdx.y;
    int d = blockIdx.x * 4 + y;
    int c = threadIdx.x;
    float dd = g_dis[d];
    float w = dd * dd;

    float4 bb = reinterpret_cast<const float4*>(b1)[c];
    float2 slo, shi;
    ldh4(&g_h1h[(size_t)d * DH + c * 4], slo, shi);
    float4 acc = make_float4(bb.x + w * slo.x, bb.y + w * slo.y,
                             bb.z + w * shi.x, bb.w + w * shi.y);

    int i = g_off[d], end = g_off[d + 1];
    for (; i + 3 < end; i += 4) {
        int s0 = g_csr_src[i], s1 = g_csr_src[i + 1];
        int s2 = g_csr_src[i + 2], s3 = g_csr_src[i + 3];
        float n0 = g_dis[s0] * dd, n1 = g_dis[s1] * dd;
        float n2 = g_dis[s2] * dd, n3 = g_dis[s3] * dd;
        float2 a0, a1, b0, b1v, c0, c1, d0, d1;
        ldh4(&g_h1h[(size_t)s0 * DH + c * 4], a0, a1);
        ldh4(&g_h1h[(size_t)s1 * DH + c * 4], b0, b1v);
        ldh4(&g_h1h[(size_t)s2 * DH + c * 4], c0, c1);
        ldh4(&g_h1h[(size_t)s3 * DH + c * 4], d0, d1);
        acc.x += n0 * a0.x + n1 * b0.x + n2 * c0.x + n3 * d0.x;
        acc.y += n0 * a0.y + n1 * b0.y + n2 * c0.y + n3 * d0.y;
        acc.z += n0 * a1.x + n1 * b1v.x + n2 * c1.x + n3 * d1.x;
        acc.w += n0 * a1.y + n1 * b1v.y + n2 * c1.y + n3 * d1.y;
    }
    for (; i < end; i++) {
        int s = g_csr_src[i];
        float nrm = g_dis[s] * dd;
        float2 v0, v1;
        ldh4(&g_h1h[(size_t)s * DH + c * 4], v0, v1);
        acc.x += nrm * v0.x; acc.y += nrm * v0.y;
        acc.z += nrm * v1.x; acc.w += nrm * v1.y;
    }

    // relu -> SMEM
    s_h[y][c * 4 + 0] = fmaxf(acc.x, 0.0f);
    s_h[y][c * 4 + 1] = fmaxf(acc.y, 0.0f);
    s_h[y][c * 4 + 2] = fmaxf(acc.z, 0.0f);
    s_h[y][c * 4 + 3] = fmaxf(acc.w, 0.0f);
    __syncthreads();

    // GEMM2 row: 47 active lanes, broadcast SMEM reads, W2 L1-resident.
    if (c < DOUT) {
        float a2 = 0.0f;
#pragma unroll 8
        for (int k = 0; k < DH; k++)
            a2 += s_h[y][k] * W2[k * DOUT + c];
        g_h2h[(size_t)d * DP + c] = __float2half_rn(a2);
    } else if (c == DOUT) {
        g_h2h[(size_t)d * DP + DOUT] = __float2half_rn(0.0f);
    }
}

// ---------------------------------------------------------------------------
// Layer-2 gather aggregation FUSED with log-softmax.
// Block (16,16): 16 nodes per block; 16 lanes per node (12 active 4-feature
// chunks of the padded 48-wide fp16 row). Reductions via width-16 shuffles.
// ---------------------------------------------------------------------------
__global__ void __launch_bounds__(256)
k_agg2g(const float* __restrict__ b2, float* __restrict__ out) {
    int d = blockIdx.x * 16 + threadIdx.y;
    int c = threadIdx.x;          // 0..15; chunks 12..15 inactive
    float dd = g_dis[d];

    float4 acc = make_float4(-INFINITY, -INFINITY, -INFINITY, -INFINITY);
    int col = c * 4;
    if (c < 12) {
        float w = dd * dd;
        float4 bb;
        bb.x = b2[col];
        bb.y = b2[col + 1];
        bb.z = b2[col + 2];
        bb.w = (col + 3 < DOUT) ? b2[col + 3] : 0.0f;
        float2 slo, shi;
        ldh4(&g_h2h[(size_t)d * DP + col], slo, shi);
        acc = make_float4(bb.x + w * slo.x, bb.y + w * slo.y,
                          bb.z + w * shi.x, bb.w + w * shi.y);
        int i = g_off[d], end = g_off[d + 1];
        for (; i + 1 < end; i += 2) {
            int s0 = g_csr_src[i];
            int s1 = g_csr_src[i + 1];
            float n0 = g_dis[s0] * dd;
            float n1 = g_dis[s1] * dd;
            float2 a0, a1, b0, b_1;
            ldh4(&g_h2h[(size_t)s0 * DP + col], a0, a1);
            ldh4(&g_h2h[(size_t)s1 * DP + col], b0, b_1);
            acc.x += n0 * a0.x + n1 * b0.x;
            acc.y += n0 * a0.y + n1 * b0.y;
            acc.z += n0 * a1.x + n1 * b_1.x;
            acc.w += n0 * a1.y + n1 * b_1.y;
        }
        if (i < end) {
            int s = g_csr_src[i];
            float nrm = g_dis[s] * dd;
            float2 v0, v1;
            ldh4(&g_h2h[(size_t)s * DP + col], v0, v1);
            acc.x += nrm * v0.x; acc.y += nrm * v0.y;
            acc.z += nrm * v1.x; acc.w += nrm * v1.y;
        }
        if (col + 3 >= DOUT) acc.w = -INFINITY;   // pad column
    }

    // log-softmax across the 16-lane group (47 valid values).
    float m = fmaxf(fmaxf(acc.x, acc.y), fmaxf(acc.z, acc.w));
#pragma unroll
    for (int o = 8; o; o >>= 1) m = fmaxf(m, __shfl_xor_sync(0xFFFFFFFFu, m, o, 16));
    float s = __expf(acc.x - m) + __expf(acc.y - m) +
              __expf(acc.z - m) + __expf(acc.w - m);   // exp(-inf)=0
#pragma unroll
    for (int o = 8; o; o >>= 1) s += __shfl_xor_sync(0xFFFFFFFFu, s, o, 16);
    float lg = m + logf(s);

    if (c < 12) {
        float* po = &out[(size_t)d * DOUT + col];
        po[0] = acc.x - lg;
        po[1] = acc.y - lg;
        po[2] = acc.z - lg;
        if (col + 3 < DOUT) po[3] = acc.w - lg;
    }
}

// ---------------------------------------------------------------------------
extern "C" void kernel_launch(void* const* d_in, const int* in_sizes, int n_in,
                              void* d_out, int out_size) {
    const float* x  = (const float*)d_in[0];
    const int*   ew = (const int*)d_in[1];    // edge_index words (int32 view)
    const float* W1 = (const float*)d_in[2];
    const float* b1 = (const float*)d_in[3];
    const float* W2 = (const float*)d_in[4];
    const float* b2 = (const float*)d_in[5];
    float* out = (float*)d_out;
    const int E = in_sizes[1] / 2;

    k_init<<<(N_NODES + 255) / 256, 256>>>();
    k_detect<<<(E + 255) / 256, 256>>>(ew, 2 * E);
    k_convX<<<(N_NODES * DIN / 8 + 255) / 256, 256>>>(x);
    k_convW1t<<<(DH * DIN + 255) / 256, 256>>>(W1);
    k_extract_count<<<(E + 255) / 256, 256>>>(ew, E);
    k_scan_dis<<<1, SCAN_T>>>();
    k_fill<<<(E + 255) / 256, 256>>>(E);

    dim3 g1(DH / 128, (N_NODES + 127) / 128);
    k_gemm1h<<<g1, 256>>>();

    k_agg1f<<<N_NODES / 4, dim3(64, 4)>>>(b1, W2);

    k_agg2g<<<N_NODES / 16, dim3(16, 16)>>>(b2, out);
}

// round 13
// speedup vs baseline: 1.3186x; 1.3186x over previous
#include <cuda_runtime.h>
#include <cuda_fp16.h>
#include <cstdint>
#include <math.h>

#define N_NODES 40000
#define DIN 512
#define DH 256
#define DOUT 47
#define DP 48            // padded layer-2 width (multiple of 4)
#define MAX_E 640000

// Scratch (no cudaMalloc allowed) — __device__ globals.
__device__ __align__(16) __half g_xh[N_NODES * DIN]; // X in fp16
__device__ __align__(16) __half g_w1t[DH * DIN];     // W1^T fp16 [n][k]
__device__ __align__(16) __half g_w2t[DP * DH];      // W2^T fp16 [n][k], padded row 47 = 0
__device__ __align__(16) __half g_h1h[N_NODES * DH]; // X @ W1 (fp16)
__device__ __align__(16) __half g_o1h[N_NODES * DH]; // relu(agg1) (fp16)
__device__ __align__(16) __half g_h2h[N_NODES * DP]; // relu(agg1) @ W2 (fp16, padded)
__device__ float g_dis[N_NODES];                     // deg^-1/2 (deg includes self-loop)
__device__ int   g_deg[N_NODES];
__device__ int   g_src[MAX_E];
__device__ int   g_dst[MAX_E];
__device__ int   g_off[N_NODES + 1];                 // CSR row offsets (by dst)
__device__ int   g_cursor[N_NODES];                  // fill cursors
__device__ int   g_csr_src[MAX_E];                   // src indices sorted by dst
__device__ int   g_is64;                             // 1 if edge_index is int64

__device__ __forceinline__ void cp16(void* smem_dst, const void* gsrc) {
    uint32_t s = (uint32_t)__cvta_generic_to_shared(smem_dst);
    asm volatile("cp.async.cg.shared.global [%0], [%1], 16;" :: "r"(s), "l"(gsrc));
}

// Load 4 consecutive halfs as 2 float2.
__device__ __forceinline__ void ldh4(const __half* p, float2& lo, float2& hi) {
    uint2 u = *reinterpret_cast<const uint2*>(p);
    lo = __half22float2(*reinterpret_cast<const __half2*>(&u.x));
    hi = __half22float2(*reinterpret_cast<const __half2*>(&u.y));
}

// ---------------------------------------------------------------------------
// Init: zero degrees + dtype flag.
// ---------------------------------------------------------------------------
__global__ void k_init() {
    int i = blockIdx.x * blockDim.x + threadIdx.x;
    if (i < N_NODES) g_deg[i] = 0;
    if (i == 0) g_is64 = 1;
}

__global__ void k_detect(const int* __restrict__ w, int nwords2E) {
    int i = blockIdx.x * blockDim.x + threadIdx.x;
    int odd = 2 * i + 1;
    if (odd < nwords2E && w[odd] != 0) g_is64 = 0;
}

// Extract indices AND count degrees in one pass.
__global__ void k_extract_count(const int* __restrict__ w, int E) {
    int e = blockIdx.x * blockDim.x + threadIdx.x;
    if (e >= E) return;
    int s, d;
    if (g_is64) {
        s = w[2 * e];
        d = w[2 * (E + e)];
    } else {
        s = w[e];
        d = w[E + e];
    }
    g_src[e] = s;
    g_dst[e] = d;
    atomicAdd(&g_deg[d], 1);
}

// ---------------------------------------------------------------------------
// Input conversions to fp16 (X full-speed; W1^T and padded W2^T together).
// ---------------------------------------------------------------------------
__global__ void __launch_bounds__(256)
k_convX(const float* __restrict__ x) {
    size_t i = ((size_t)blockIdx.x * 256 + threadIdx.x) * 8;
    float4 v0 = *reinterpret_cast<const float4*>(&x[i]);
    float4 v1 = *reinterpret_cast<const float4*>(&x[i + 4]);
    __half2 h[4];
    h[0] = __floats2half2_rn(v0.x, v0.y);
    h[1] = __floats2half2_rn(v0.z, v0.w);
    h[2] = __floats2half2_rn(v1.x, v1.y);
    h[3] = __floats2half2_rn(v1.z, v1.w);
    *reinterpret_cast<uint4*>(&g_xh[i]) = *reinterpret_cast<uint4*>(h);
}

__global__ void __launch_bounds__(256)
k_convW(const float* __restrict__ W1, const float* __restrict__ W2) {
    int idx = blockIdx.x * 256 + threadIdx.x;
    if (idx < DH * DIN) {
        int n = idx / DIN, k = idx % DIN;
        g_w1t[idx] = __float2half_rn(W1[(size_t)k * DH + n]);
    } else if (idx < DH * DIN + DP * DH) {
        int j = idx - DH * DIN;
        int n = j / DH, k = j % DH;
        g_w2t[j] = (n < DOUT) ? __float2half_rn(W2[(size_t)k * DOUT + n])
                              : __float2half_rn(0.0f);
    }
}

// ---------------------------------------------------------------------------
// Prefix scan over g_deg -> g_off + cursors + dis (single block).
// ---------------------------------------------------------------------------
#define SCAN_T 1024
#define SCAN_PER ((N_NODES + SCAN_T - 1) / SCAN_T)   // 40
__global__ void __launch_bounds__(SCAN_T)
k_scan_dis() {
    __shared__ int part[SCAN_T];
    int t = threadIdx.x;
    int base = t * SCAN_PER;
    int sum = 0;
#pragma unroll 4
    for (int i = 0; i < SCAN_PER; i++) {
        int idx = base + i;
        if (idx < N_NODES) sum += g_deg[idx];
    }
    part[t] = sum;
    __syncthreads();
    for (int o = 1; o < SCAN_T; o <<= 1) {
        int v = (t >= o) ? part[t - o] : 0;
        __syncthreads();
        part[t] += v;
        __syncthreads();
    }
    int off = (t == 0) ? 0 : part[t - 1];
    for (int i = 0; i < SCAN_PER; i++) {
        int idx = base + i;
        if (idx < N_NODES) {
            g_off[idx] = off;
            g_cursor[idx] = off;
            off += g_deg[idx];
            g_dis[idx] = rsqrtf((float)g_deg[idx] + 1.0f);  // +1 = self loop
        }
    }
    if (t == SCAN_T - 1) g_off[N_NODES] = off;
}

__global__ void k_fill(int E) {
    int e = blockIdx.x * blockDim.x + threadIdx.x;
    if (e >= E) return;
    int d = g_dst[e];
    int pos = atomicAdd(&g_cursor[d], 1);
    g_csr_src[pos] = g_src[e];
}

// ---------------------------------------------------------------------------
// fp16 MMA m16n8k16
// ---------------------------------------------------------------------------
__device__ __forceinline__ void mma_f16(float* c, const uint32_t* a, const uint32_t* b) {
    asm volatile(
        "mma.sync.aligned.m16n8k16.row.col.f32.f16.f16.f32 "
        "{%0,%1,%2,%3}, {%4,%5,%6,%7}, {%8,%9}, {%0,%1,%2,%3};"
        : "+f"(c[0]), "+f"(c[1]), "+f"(c[2]), "+f"(c[3])
        : "r"(a[0]), "r"(a[1]), "r"(a[2]), "r"(a[3]),
          "r"(b[0]), "r"(b[1]));
}

// ---------------------------------------------------------------------------
// GEMM1 (fp16 tensor cores, cp.async double-buffered):
//   h1 = X[40000,512] @ W1[512,256], fp16 in / fp32 accum / fp16 out.
// Block 128x128, 256 threads, 8 warps (4x2), warp tile 32x64, BK=32.
// ---------------------------------------------------------------------------
#define BKH 32
#define NKTH (DIN / BKH)   // 16
__global__ void __launch_bounds__(256, 2)
k_gemm1h() {
    __shared__ __half As[2][128][BKH + 8];
    __shared__ __half Bs[2][128][BKH + 8];

    const int tid = threadIdx.x;
    const int warp = tid >> 5, lane = tid & 31;
    const int gid = lane >> 2, tig = lane & 3;
    const int warpRow = warp >> 1, warpCol = warp & 1;
    const int bm = blockIdx.y * 128;
    const int bn = blockIdx.x * 128;

    const int r0 = tid >> 2,          c0 = (tid & 3) * 8;
    const int r1 = (tid + 256) >> 2,  c1 = c0;
    const int ag0 = (bm + r0 < N_NODES) ? bm + r0 : N_NODES - 1;
    const int ag1 = (bm + r1 < N_NODES) ? bm + r1 : N_NODES - 1;

    float acc[2][8][4];
#pragma unroll
    for (int mi = 0; mi < 2; mi++)
#pragma unroll
        for (int ni = 0; ni < 8; ni++)
#pragma unroll
            for (int r = 0; r < 4; r++) acc[mi][ni][r] = 0.0f;

    {
        cp16(&As[0][r0][c0], &g_xh[(size_t)ag0 * DIN + c0]);
        cp16(&As[0][r1][c1], &g_xh[(size_t)ag1 * DIN + c1]);
        cp16(&Bs[0][r0][c0], &g_w1t[(size_t)(bn + r0) * DIN + c0]);
        cp16(&Bs[0][r1][c1], &g_w1t[(size_t)(bn + r1) * DIN + c1]);
        asm volatile("cp.async.commit_group;");
    }

    int buf = 0;
    for (int kt = 0; kt < NKTH; kt++) {
        if (kt + 1 < NKTH) {
            int k0 = (kt + 1) * BKH;
            int nb = buf ^ 1;
            cp16(&As[nb][r0][c0], &g_xh[(size_t)ag0 * DIN + k0 + c0]);
            cp16(&As[nb][r1][c1], &g_xh[(size_t)ag1 * DIN + k0 + c1]);
            cp16(&Bs[nb][r0][c0], &g_w1t[(size_t)(bn + r0) * DIN + k0 + c0]);
            cp16(&Bs[nb][r1][c1], &g_w1t[(size_t)(bn + r1) * DIN + k0 + c1]);
            asm volatile("cp.async.commit_group;");
            asm volatile("cp.async.wait_group 1;");
        } else {
            asm volatile("cp.async.wait_group 0;");
        }
        __syncthreads();

#pragma unroll
        for (int kk = 0; kk < 2; kk++) {
            int kb = kk * 16 + tig * 2;
            uint32_t a[2][4], b[8][2];
#pragma unroll
            for (int mi = 0; mi < 2; mi++) {
                int r = warpRow * 32 + mi * 16 + gid;
                a[mi][0] = *reinterpret_cast<const uint32_t*>(&As[buf][r][kb]);
                a[mi][1] = *reinterpret_cast<const uint32_t*>(&As[buf][r + 8][kb]);
                a[mi][2] = *reinterpret_cast<const uint32_t*>(&As[buf][r][kb + 8]);
                a[mi][3] = *reinterpret_cast<const uint32_t*>(&As[buf][r + 8][kb + 8]);
            }
#pragma unroll
            for (int ni = 0; ni < 8; ni++) {
                int c = warpCol * 64 + ni * 8 + gid;
                b[ni][0] = *reinterpret_cast<const uint32_t*>(&Bs[buf][c][kb]);
                b[ni][1] = *reinterpret_cast<const uint32_t*>(&Bs[buf][c][kb + 8]);
            }
#pragma unroll
            for (int mi = 0; mi < 2; mi++)
#pragma unroll
                for (int ni = 0; ni < 8; ni++)
                    mma_f16(acc[mi][ni], a[mi], b[ni]);
        }
        __syncthreads();
        buf ^= 1;
    }

#pragma unroll
    for (int mi = 0; mi < 2; mi++) {
        int row0 = bm + warpRow * 32 + mi * 16 + gid;
        int row1 = row0 + 8;
#pragma unroll
        for (int ni = 0; ni < 8; ni++) {
            int col = bn + warpCol * 64 + ni * 8 + tig * 2;
            if (row0 < N_NODES)
                *reinterpret_cast<__half2*>(&g_h1h[(size_t)row0 * DH + col]) =
                    __floats2half2_rn(acc[mi][ni][0], acc[mi][ni][1]);
            if (row1 < N_NODES)
                *reinterpret_cast<__half2*>(&g_h1h[(size_t)row1 * DH + col]) =
                    __floats2half2_rn(acc[mi][ni][2], acc[mi][ni][3]);
        }
    }
}

// ---------------------------------------------------------------------------
// Layer-1 gather aggregation + relu, fp16 out:
//   o1h[d] = relu(b1 + dis[d]^2*h1[d] + sum_s nrm*h1[s])
// Block (64,4): 4 nodes per block, 64 lanes = 4-feature chunks of 256.
// fp16 gather, fp32 accumulate, x4 unrolled for MLP.
// ---------------------------------------------------------------------------
__global__ void __launch_bounds__(256)
k_agg1g(const float* __restrict__ b1) {
    int d = blockIdx.x * 4 + threadIdx.y;
    int c = threadIdx.x;
    float dd = g_dis[d];
    float w = dd * dd;

    float4 bb = reinterpret_cast<const float4*>(b1)[c];
    float2 slo, shi;
    ldh4(&g_h1h[(size_t)d * DH + c * 4], slo, shi);
    float4 acc = make_float4(bb.x + w * slo.x, bb.y + w * slo.y,
                             bb.z + w * shi.x, bb.w + w * shi.y);

    int i = g_off[d], end = g_off[d + 1];
    for (; i + 3 < end; i += 4) {
        int s0 = g_csr_src[i], s1 = g_csr_src[i + 1];
        int s2 = g_csr_src[i + 2], s3 = g_csr_src[i + 3];
        float n0 = g_dis[s0] * dd, n1 = g_dis[s1] * dd;
        float n2 = g_dis[s2] * dd, n3 = g_dis[s3] * dd;
        float2 a0, a1, b0, b1v, c0, c1, d0, d1;
        ldh4(&g_h1h[(size_t)s0 * DH + c * 4], a0, a1);
        ldh4(&g_h1h[(size_t)s1 * DH + c * 4], b0, b1v);
        ldh4(&g_h1h[(size_t)s2 * DH + c * 4], c0, c1);
        ldh4(&g_h1h[(size_t)s3 * DH + c * 4], d0, d1);
        acc.x += n0 * a0.x + n1 * b0.x + n2 * c0.x + n3 * d0.x;
        acc.y += n0 * a0.y + n1 * b0.y + n2 * c0.y + n3 * d0.y;
        acc.z += n0 * a1.x + n1 * b1v.x + n2 * c1.x + n3 * d1.x;
        acc.w += n0 * a1.y + n1 * b1v.y + n2 * c1.y + n3 * d1.y;
    }
    for (; i < end; i++) {
        int s = g_csr_src[i];
        float nrm = g_dis[s] * dd;
        float2 v0, v1;
        ldh4(&g_h1h[(size_t)s * DH + c * 4], v0, v1);
        acc.x += nrm * v0.x; acc.y += nrm * v0.y;
        acc.z += nrm * v1.x; acc.w += nrm * v1.y;
    }

    __half2 h0 = __floats2half2_rn(fmaxf(acc.x, 0.0f), fmaxf(acc.y, 0.0f));
    __half2 h1 = __floats2half2_rn(fmaxf(acc.z, 0.0f), fmaxf(acc.w, 0.0f));
    uint2 u;
    u.x = *reinterpret_cast<uint32_t*>(&h0);
    u.y = *reinterpret_cast<uint32_t*>(&h1);
    *reinterpret_cast<uint2*>(&g_o1h[(size_t)d * DH + c * 4]) = u;
}

// ---------------------------------------------------------------------------
// GEMM2 (fp16 tensor cores): h2 = o1h[40000,256] @ W2[256,47->48 pad]
// Block 128 rows; W2^T (48x256) fully SMEM-resident; A staged BK=64.
// 8 warps, each 16 rows x 48 cols. fp32 accum, fp16 out (padded col = 0).
// ---------------------------------------------------------------------------
#define BK2 64
#define NKT2 (DH / BK2)   // 4
__global__ void __launch_bounds__(256, 1)
k_gemm2h() {
    __shared__ __half As[128][BK2 + 8];
    __shared__ __half Bsw[DP][DH + 8];

    const int tid = threadIdx.x;
    const int warp = tid >> 5, lane = tid & 31;
    const int gid = lane >> 2, tig = lane & 3;
    const int bm = blockIdx.x * 128;

    // Load full W2^T: 48 x 256 halfs = 1536 16B-chunks, 6 per thread.
    for (int i = tid; i < DP * DH / 8; i += 256) {
        int n = (i * 8) / DH, k = (i * 8) % DH;
        cp16(&Bsw[n][k], &g_w2t[n * DH + k]);
    }

    // A-tile mapping: 128 rows x 64 halfs = 1024 chunks, 4 per thread.
    float acc[6][4];
#pragma unroll
    for (int ni = 0; ni < 6; ni++)
#pragma unroll
        for (int r = 0; r < 4; r++) acc[ni][r] = 0.0f;

    for (int kt = 0; kt < NKT2; kt++) {
        int k0 = kt * BK2;
#pragma unroll
        for (int j = 0; j < 4; j++) {
            int i = tid + j * 256;
            int r = i >> 3, cc = (i & 7) * 8;
            int ar = (bm + r < N_NODES) ? bm + r : N_NODES - 1;
            cp16(&As[r][cc], &g_o1h[(size_t)ar * DH + k0 + cc]);
        }
        asm volatile("cp.async.commit_group;");
        asm volatile("cp.async.wait_group 0;");
        __syncthreads();

#pragma unroll
        for (int kk = 0; kk < 4; kk++) {
            int kb = kk * 16 + tig * 2;
            int r = warp * 16 + gid;
            uint32_t a[4], b[6][2];
            a[0] = *reinterpret_cast<const uint32_t*>(&As[r][kb]);
            a[1] = *reinterpret_cast<const uint32_t*>(&As[r + 8][kb]);
            a[2] = *reinterpret_cast<const uint32_t*>(&As[r][kb + 8]);
            a[3] = *reinterpret_cast<const uint32_t*>(&As[r + 8][kb + 8]);
            int kg = k0 + kk * 16 + tig * 2;
#pragma unroll
            for (int ni = 0; ni < 6; ni++) {
                int c = ni * 8 + gid;
                b[ni][0] = *reinterpret_cast<const uint32_t*>(&Bsw[c][kg]);
                b[ni][1] = *reinterpret_cast<const uint32_t*>(&Bsw[c][kg + 8]);
            }
#pragma unroll
            for (int ni = 0; ni < 6; ni++)
                mma_f16(acc[ni], a, b[ni]);
        }
        __syncthreads();
    }

    int row0 = bm + warp * 16 + gid;
    int row1 = row0 + 8;
#pragma unroll
    for (int ni = 0; ni < 6; ni++) {
        int col = ni * 8 + tig * 2;
        if (row0 < N_NODES)
            *reinterpret_cast<__half2*>(&g_h2h[(size_t)row0 * DP + col]) =
                __floats2half2_rn(acc[ni][0], acc[ni][1]);
        if (row1 < N_NODES)
            *reinterpret_cast<__half2*>(&g_h2h[(size_t)row1 * DP + col]) =
                __floats2half2_rn(acc[ni][2], acc[ni][3]);
    }
}

// ---------------------------------------------------------------------------
// Layer-2 gather aggregation FUSED with log-softmax.
// Block (16,16): 16 nodes per block; 16 lanes per node (12 active 4-feature
// chunks of the padded 48-wide fp16 row). Reductions via width-16 shuffles.
// ---------------------------------------------------------------------------
__global__ void __launch_bounds__(256)
k_agg2g(const float* __restrict__ b2, float* __restrict__ out) {
    int d = blockIdx.x * 16 + threadIdx.y;
    int c = threadIdx.x;          // 0..15; chunks 12..15 inactive
    float dd = g_dis[d];

    float4 acc = make_float4(-INFINITY, -INFINITY, -INFINITY, -INFINITY);
    int col = c * 4;
    if (c < 12) {
        float w = dd * dd;
        float4 bb;
        bb.x = b2[col];
        bb.y = b2[col + 1];
        bb.z = b2[col + 2];
        bb.w = (col + 3 < DOUT) ? b2[col + 3] : 0.0f;
        float2 slo, shi;
        ldh4(&g_h2h[(size_t)d * DP + col], slo, shi);
        acc = make_float4(bb.x + w * slo.x, bb.y + w * slo.y,
                          bb.z + w * shi.x, bb.w + w * shi.y);
        int i = g_off[d], end = g_off[d + 1];
        for (; i + 1 < end; i += 2) {
            int s0 = g_csr_src[i];
            int s1 = g_csr_src[i + 1];
            float n0 = g_dis[s0] * dd;
            float n1 = g_dis[s1] * dd;
            float2 a0, a1, b0, b_1;
            ldh4(&g_h2h[(size_t)s0 * DP + col], a0, a1);
            ldh4(&g_h2h[(size_t)s1 * DP + col], b0, b_1);
            acc.x += n0 * a0.x + n1 * b0.x;
            acc.y += n0 * a0.y + n1 * b0.y;
            acc.z += n0 * a1.x + n1 * b_1.x;
            acc.w += n0 * a1.y + n1 * b_1.y;
        }
        if (i < end) {
            int s = g_csr_src[i];
            float nrm = g_dis[s] * dd;
            float2 v0, v1;
            ldh4(&g_h2h[(size_t)s * DP + col], v0, v1);
            acc.x += nrm * v0.x; acc.y += nrm * v0.y;
            acc.z += nrm * v1.x; acc.w += nrm * v1.y;
        }
        if (col + 3 >= DOUT) acc.w = -INFINITY;   // pad column
    }

    // log-softmax across the 16-lane group (47 valid values).
    float m = fmaxf(fmaxf(acc.x, acc.y), fmaxf(acc.z, acc.w));
#pragma unroll
    for (int o = 8; o; o >>= 1) m = fmaxf(m, __shfl_xor_sync(0xFFFFFFFFu, m, o, 16));
    float s = __expf(acc.x - m) + __expf(acc.y - m) +
              __expf(acc.z - m) + __expf(acc.w - m);   // exp(-inf)=0
#pragma unroll
    for (int o = 8; o; o >>= 1) s += __shfl_xor_sync(0xFFFFFFFFu, s, o, 16);
    float lg = m + logf(s);

    if (c < 12) {
        float* po = &out[(size_t)d * DOUT + col];
        po[0] = acc.x - lg;
        po[1] = acc.y - lg;
        po[2] = acc.z - lg;
        if (col + 3 < DOUT) po[3] = acc.w - lg;
    }
}

// ---------------------------------------------------------------------------
extern "C" void kernel_launch(void* const* d_in, const int* in_sizes, int n_in,
                              void* d_out, int out_size) {
    const float* x  = (const float*)d_in[0];
    const int*   ew = (const int*)d_in[1];    // edge_index words (int32 view)
    const float* W1 = (const float*)d_in[2];
    const float* b1 = (const float*)d_in[3];
    const float* W2 = (const float*)d_in[4];
    const float* b2 = (const float*)d_in[5];
    float* out = (float*)d_out;
    const int E = in_sizes[1] / 2;

    k_init<<<(N_NODES + 255) / 256, 256>>>();
    k_detect<<<(E + 255) / 256, 256>>>(ew, 2 * E);
    k_convX<<<(N_NODES * DIN / 8 + 255) / 256, 256>>>(x);
    k_convW<<<(DH * DIN + DP * DH + 255) / 256, 256>>>(W1, W2);
    k_extract_count<<<(E + 255) / 256, 256>>>(ew, E);
    k_scan_dis<<<1, SCAN_T>>>();
    k_fill<<<(E + 255) / 256, 256>>>(E);

    dim3 g1(DH / 128, (N_NODES + 127) / 128);
    k_gemm1h<<<g1, 256>>>();

    k_agg1g<<<N_NODES / 4, dim3(64, 4)>>>(b1);

    k_gemm2h<<<(N_NODES + 127) / 128, 256>>>();

    k_agg2g<<<N_NODES / 16, dim3(16, 16)>>>(b2, out);
}

// round 16
// speedup vs baseline: 1.4442x; 1.0952x over previous
#include <cuda_runtime.h>
#include <cuda_fp16.h>
#include <cstdint>
#include <math.h>

#define N_NODES 40000
#define DIN 512
#define DH 256
#define DOUT 47
#define DP 48            // padded layer-2 width (multiple of 4)
#define MAX_E 640000

// Scratch (no cudaMalloc allowed) — __device__ globals.
__device__ __align__(16) __half g_xh[N_NODES * DIN]; // X in fp16
__device__ __align__(16) __half g_w1t[DH * DIN];     // W1^T fp16 [n][k]
__device__ __align__(16) __half g_w2t[DP * DH];      // W2^T fp16 [n][k], padded row 47 = 0
__device__ __align__(16) __half g_h1h[N_NODES * DH]; // X @ W1 (fp16)
__device__ __align__(16) __half g_o1h[N_NODES * DH]; // relu(agg1) (fp16)
__device__ __align__(16) __half g_h2h[N_NODES * DP]; // relu(agg1) @ W2 (fp16, padded)
__device__ float g_dis[N_NODES];                     // deg^-1/2 (deg includes self-loop)
__device__ int   g_deg[N_NODES];
__device__ int   g_src[MAX_E];
__device__ int   g_dst[MAX_E];
__device__ int   g_off[N_NODES + 1];                 // CSR row offsets (by dst)
__device__ int   g_cursor[N_NODES];                  // fill cursors
__device__ int   g_csr_src[MAX_E];                   // src indices sorted by dst
__device__ int   g_is64;                             // 1 if edge_index is int64

__device__ __forceinline__ void cp16(void* smem_dst, const void* gsrc) {
    uint32_t s = (uint32_t)__cvta_generic_to_shared(smem_dst);
    asm volatile("cp.async.cg.shared.global [%0], [%1], 16;" :: "r"(s), "l"(gsrc));
}

// Load 8 consecutive halfs (16B) and accumulate into 8 fp32 with weight n.
__device__ __forceinline__ void acc8(float* acc, const __half* p, float n) {
    uint4 u = *reinterpret_cast<const uint4*>(p);
    const __half2* h = reinterpret_cast<const __half2*>(&u);
#pragma unroll
    for (int j = 0; j < 4; j++) {
        float2 f = __half22float2(h[j]);
        acc[2 * j] += n * f.x;
        acc[2 * j + 1] += n * f.y;
    }
}

// Load 4 consecutive halfs as 2 float2.
__device__ __forceinline__ void ldh4(const __half* p, float2& lo, float2& hi) {
    uint2 u = *reinterpret_cast<const uint2*>(p);
    lo = __half22float2(*reinterpret_cast<const __half2*>(&u.x));
    hi = __half22float2(*reinterpret_cast<const __half2*>(&u.y));
}

// ---------------------------------------------------------------------------
// Init (zero degrees) + dtype detection (block 0, sampled, race-free).
// ---------------------------------------------------------------------------
__global__ void k_initdet(const int* __restrict__ w) {
    int i = blockIdx.x * blockDim.x + threadIdx.x;
    if (i < N_NODES) g_deg[i] = 0;
    if (blockIdx.x == 0) {
        __shared__ int nz;
        if (threadIdx.x == 0) nz = 0;
        __syncthreads();
        int local = 0;
#pragma unroll
        for (int j = 0; j < 8; j++) {
            int odd = 2 * (threadIdx.x * 8 + j) + 1;   // < 4096 < 2E words, safe
            if (w[odd] != 0) local = 1;
        }
        if (local) atomicOr(&nz, 1);
        __syncthreads();
        if (threadIdx.x == 0) g_is64 = (nz == 0);
    }
}

// Extract indices AND count degrees in one pass.
__global__ void k_extract_count(const int* __restrict__ w, int E) {
    int e = blockIdx.x * blockDim.x + threadIdx.x;
    if (e >= E) return;
    int s, d;
    if (g_is64) {
        s = w[2 * e];
        d = w[2 * (E + e)];
    } else {
        s = w[e];
        d = w[E + e];
    }
    g_src[e] = s;
    g_dst[e] = d;
    atomicAdd(&g_deg[d], 1);
}

// ---------------------------------------------------------------------------
// Input conversions to fp16 (X full-speed; W1^T and padded W2^T together).
// ---------------------------------------------------------------------------
__global__ void __launch_bounds__(256)
k_convX(const float* __restrict__ x) {
    size_t i = ((size_t)blockIdx.x * 256 + threadIdx.x) * 8;
    float4 v0 = *reinterpret_cast<const float4*>(&x[i]);
    float4 v1 = *reinterpret_cast<const float4*>(&x[i + 4]);
    __half2 h[4];
    h[0] = __floats2half2_rn(v0.x, v0.y);
    h[1] = __floats2half2_rn(v0.z, v0.w);
    h[2] = __floats2half2_rn(v1.x, v1.y);
    h[3] = __floats2half2_rn(v1.z, v1.w);
    *reinterpret_cast<uint4*>(&g_xh[i]) = *reinterpret_cast<uint4*>(h);
}

__global__ void __launch_bounds__(256)
k_convW(const float* __restrict__ W1, const float* __restrict__ W2) {
    int idx = blockIdx.x * 256 + threadIdx.x;
    if (idx < DH * DIN) {
        int n = idx / DIN, k = idx % DIN;
        g_w1t[idx] = __float2half_rn(W1[(size_t)k * DH + n]);
    } else if (idx < DH * DIN + DP * DH) {
        int j = idx - DH * DIN;
        int n = j / DH, k = j % DH;
        g_w2t[j] = (n < DOUT) ? __float2half_rn(W2[(size_t)k * DOUT + n])
                              : __float2half_rn(0.0f);
    }
}

// ---------------------------------------------------------------------------
// Prefix scan over g_deg -> g_off + cursors + dis (single block).
// ---------------------------------------------------------------------------
#define SCAN_T 1024
#define SCAN_PER ((N_NODES + SCAN_T - 1) / SCAN_T)   // 40
__global__ void __launch_bounds__(SCAN_T)
k_scan_dis() {
    __shared__ int part[SCAN_T];
    int t = threadIdx.x;
    int base = t * SCAN_PER;
    int sum = 0;
#pragma unroll 4
    for (int i = 0; i < SCAN_PER; i++) {
        int idx = base + i;
        if (idx < N_NODES) sum += g_deg[idx];
    }
    part[t] = sum;
    __syncthreads();
    for (int o = 1; o < SCAN_T; o <<= 1) {
        int v = (t >= o) ? part[t - o] : 0;
        __syncthreads();
        part[t] += v;
        __syncthreads();
    }
    int off = (t == 0) ? 0 : part[t - 1];
    for (int i = 0; i < SCAN_PER; i++) {
        int idx = base + i;
        if (idx < N_NODES) {
            g_off[idx] = off;
            g_cursor[idx] = off;
            off += g_deg[idx];
            g_dis[idx] = rsqrtf((float)g_deg[idx] + 1.0f);  // +1 = self loop
        }
    }
    if (t == SCAN_T - 1) g_off[N_NODES] = off;
}

__global__ void k_fill(int E) {
    int e = blockIdx.x * blockDim.x + threadIdx.x;
    if (e >= E) return;
    int d = g_dst[e];
    int pos = atomicAdd(&g_cursor[d], 1);
    g_csr_src[pos] = g_src[e];
}

// ---------------------------------------------------------------------------
// fp16 MMA m16n8k16
// ---------------------------------------------------------------------------
__device__ __forceinline__ void mma_f16(float* c, const uint32_t* a, const uint32_t* b) {
    asm volatile(
        "mma.sync.aligned.m16n8k16.row.col.f32.f16.f16.f32 "
        "{%0,%1,%2,%3}, {%4,%5,%6,%7}, {%8,%9}, {%0,%1,%2,%3};"
        : "+f"(c[0]), "+f"(c[1]), "+f"(c[2]), "+f"(c[3])
        : "r"(a[0]), "r"(a[1]), "r"(a[2]), "r"(a[3]),
          "r"(b[0]), "r"(b[1]));
}

// ---------------------------------------------------------------------------
// GEMM1 (fp16 tensor cores, cp.async double-buffered):
//   h1 = X[40000,512] @ W1[512,256], fp16 in / fp32 accum / fp16 out.
// Block 128x128, 256 threads, 8 warps (4x2), warp tile 32x64, BK=32.
// ---------------------------------------------------------------------------
#define BKH 32
#define NKTH (DIN / BKH)   // 16
__global__ void __launch_bounds__(256, 2)
k_gemm1h() {
    __shared__ __half As[2][128][BKH + 8];
    __shared__ __half Bs[2][128][BKH + 8];

    const int tid = threadIdx.x;
    const int warp = tid >> 5, lane = tid & 31;
    const int gid = lane >> 2, tig = lane & 3;
    const int warpRow = warp >> 1, warpCol = warp & 1;
    const int bm = blockIdx.y * 128;
    const int bn = blockIdx.x * 128;

    const int r0 = tid >> 2,          c0 = (tid & 3) * 8;
    const int r1 = (tid + 256) >> 2,  c1 = c0;
    const int ag0 = (bm + r0 < N_NODES) ? bm + r0 : N_NODES - 1;
    const int ag1 = (bm + r1 < N_NODES) ? bm + r1 : N_NODES - 1;

    float acc[2][8][4];
#pragma unroll
    for (int mi = 0; mi < 2; mi++)
#pragma unroll
        for (int ni = 0; ni < 8; ni++)
#pragma unroll
            for (int r = 0; r < 4; r++) acc[mi][ni][r] = 0.0f;

    {
        cp16(&As[0][r0][c0], &g_xh[(size_t)ag0 * DIN + c0]);
        cp16(&As[0][r1][c1], &g_xh[(size_t)ag1 * DIN + c1]);
        cp16(&Bs[0][r0][c0], &g_w1t[(size_t)(bn + r0) * DIN + c0]);
        cp16(&Bs[0][r1][c1], &g_w1t[(size_t)(bn + r1) * DIN + c1]);
        asm volatile("cp.async.commit_group;");
    }

    int buf = 0;
    for (int kt = 0; kt < NKTH; kt++) {
        if (kt + 1 < NKTH) {
            int k0 = (kt + 1) * BKH;
            int nb = buf ^ 1;
            cp16(&As[nb][r0][c0], &g_xh[(size_t)ag0 * DIN + k0 + c0]);
            cp16(&As[nb][r1][c1], &g_xh[(size_t)ag1 * DIN + k0 + c1]);
            cp16(&Bs[nb][r0][c0], &g_w1t[(size_t)(bn + r0) * DIN + k0 + c0]);
            cp16(&Bs[nb][r1][c1], &g_w1t[(size_t)(bn + r1) * DIN + k0 + c1]);
            asm volatile("cp.async.commit_group;");
            asm volatile("cp.async.wait_group 1;");
        } else {
            asm volatile("cp.async.wait_group 0;");
        }
        __syncthreads();

#pragma unroll
        for (int kk = 0; kk < 2; kk++) {
            int kb = kk * 16 + tig * 2;
            uint32_t a[2][4], b[8][2];
#pragma unroll
            for (int mi = 0; mi < 2; mi++) {
                int r = warpRow * 32 + mi * 16 + gid;
                a[mi][0] = *reinterpret_cast<const uint32_t*>(&As[buf][r][kb]);
                a[mi][1] = *reinterpret_cast<const uint32_t*>(&As[buf][r + 8][kb]);
                a[mi][2] = *reinterpret_cast<const uint32_t*>(&As[buf][r][kb + 8]);
                a[mi][3] = *reinterpret_cast<const uint32_t*>(&As[buf][r + 8][kb + 8]);
            }
#pragma unroll
            for (int ni = 0; ni < 8; ni++) {
                int c = warpCol * 64 + ni * 8 + gid;
                b[ni][0] = *reinterpret_cast<const uint32_t*>(&Bs[buf][c][kb]);
                b[ni][1] = *reinterpret_cast<const uint32_t*>(&Bs[buf][c][kb + 8]);
            }
#pragma unroll
            for (int mi = 0; mi < 2; mi++)
#pragma unroll
                for (int ni = 0; ni < 8; ni++)
                    mma_f16(acc[mi][ni], a[mi], b[ni]);
        }
        __syncthreads();
        buf ^= 1;
    }

#pragma unroll
    for (int mi = 0; mi < 2; mi++) {
        int row0 = bm + warpRow * 32 + mi * 16 + gid;
        int row1 = row0 + 8;
#pragma unroll
        for (int ni = 0; ni < 8; ni++) {
            int col = bn + warpCol * 64 + ni * 8 + tig * 2;
            if (row0 < N_NODES)
                *reinterpret_cast<__half2*>(&g_h1h[(size_t)row0 * DH + col]) =
                    __floats2half2_rn(acc[mi][ni][0], acc[mi][ni][1]);
            if (row1 < N_NODES)
                *reinterpret_cast<__half2*>(&g_h1h[(size_t)row1 * DH + col]) =
                    __floats2half2_rn(acc[mi][ni][2], acc[mi][ni][3]);
        }
    }
}

// ---------------------------------------------------------------------------
// Layer-1 gather aggregation + relu, fp16 out:
//   o1h[d] = relu(b1 + dis[d]^2*h1[d] + sum_s nrm*h1[s])
// Block (32,8): one warp per node, lane = 8-feature chunk (uint4 loads).
// fp16 gather, fp32 accumulate, x4 neighbor unroll for MLP.
// ---------------------------------------------------------------------------
__global__ void __launch_bounds__(256)
k_agg1g(const float* __restrict__ b1) {
    int d = blockIdx.x * 8 + threadIdx.y;
    int c = threadIdx.x;              // 0..31, chunk of 8 features
    const __half* base = &g_h1h[(size_t)c * 8];
    float dd = g_dis[d];
    float w = dd * dd;

    float acc[8];
    {
        float4 b0 = reinterpret_cast<const float4*>(b1)[c * 2];
        float4 b1v = reinterpret_cast<const float4*>(b1)[c * 2 + 1];
        acc[0] = b0.x; acc[1] = b0.y; acc[2] = b0.z; acc[3] = b0.w;
        acc[4] = b1v.x; acc[5] = b1v.y; acc[6] = b1v.z; acc[7] = b1v.w;
    }
    acc8(acc, base + (size_t)d * DH, w);   // self loop

    int i = g_off[d], end = g_off[d + 1];
    for (; i + 3 < end; i += 4) {
        int s0 = g_csr_src[i], s1 = g_csr_src[i + 1];
        int s2 = g_csr_src[i + 2], s3 = g_csr_src[i + 3];
        float n0 = g_dis[s0] * dd, n1 = g_dis[s1] * dd;
        float n2 = g_dis[s2] * dd, n3 = g_dis[s3] * dd;
        acc8(acc, base + (size_t)s0 * DH, n0);
        acc8(acc, base + (size_t)s1 * DH, n1);
        acc8(acc, base + (size_t)s2 * DH, n2);
        acc8(acc, base + (size_t)s3 * DH, n3);
    }
    for (; i < end; i++) {
        int s = g_csr_src[i];
        acc8(acc, base + (size_t)s * DH, g_dis[s] * dd);
    }

    __half2 h[4];
#pragma unroll
    for (int j = 0; j < 4; j++)
        h[j] = __floats2half2_rn(fmaxf(acc[2 * j], 0.0f), fmaxf(acc[2 * j + 1], 0.0f));
    *reinterpret_cast<uint4*>(&g_o1h[(size_t)d * DH + c * 8]) =
        *reinterpret_cast<uint4*>(h);
}

// ---------------------------------------------------------------------------
// GEMM2 (fp16 tensor cores): h2 = o1h[40000,256] @ W2[256,47->48 pad]
// Block 128 rows; W2^T (48x256) fully SMEM-resident; A staged BK=64.
// ---------------------------------------------------------------------------
#define BK2 64
#define NKT2 (DH / BK2)   // 4
__global__ void __launch_bounds__(256, 1)
k_gemm2h() {
    __shared__ __half As[128][BK2 + 8];
    __shared__ __half Bsw[DP][DH + 8];

    const int tid = threadIdx.x;
    const int warp = tid >> 5, lane = tid & 31;
    const int gid = lane >> 2, tig = lane & 3;
    const int bm = blockIdx.x * 128;

    for (int i = tid; i < DP * DH / 8; i += 256) {
        int n = (i * 8) / DH, k = (i * 8) % DH;
        cp16(&Bsw[n][k], &g_w2t[n * DH + k]);
    }

    float acc[6][4];
#pragma unroll
    for (int ni = 0; ni < 6; ni++)
#pragma unroll
        for (int r = 0; r < 4; r++) acc[ni][r] = 0.0f;

    for (int kt = 0; kt < NKT2; kt++) {
        int k0 = kt * BK2;
#pragma unroll
        for (int j = 0; j < 4; j++) {
            int i = tid + j * 256;
            int r = i >> 3, cc = (i & 7) * 8;
            int ar = (bm + r < N_NODES) ? bm + r : N_NODES - 1;
            cp16(&As[r][cc], &g_o1h[(size_t)ar * DH + k0 + cc]);
        }
        asm volatile("cp.async.commit_group;");
        asm volatile("cp.async.wait_group 0;");
        __syncthreads();

#pragma unroll
        for (int kk = 0; kk < 4; kk++) {
            int kb = kk * 16 + tig * 2;
            int r = warp * 16 + gid;
            uint32_t a[4], b[6][2];
            a[0] = *reinterpret_cast<const uint32_t*>(&As[r][kb]);
            a[1] = *reinterpret_cast<const uint32_t*>(&As[r + 8][kb]);
            a[2] = *reinterpret_cast<const uint32_t*>(&As[r][kb + 8]);
            a[3] = *reinterpret_cast<const uint32_t*>(&As[r + 8][kb + 8]);
            int kg = k0 + kk * 16 + tig * 2;
#pragma unroll
            for (int ni = 0; ni < 6; ni++) {
                int c = ni * 8 + gid;
                b[ni][0] = *reinterpret_cast<const uint32_t*>(&Bsw[c][kg]);
                b[ni][1] = *reinterpret_cast<const uint32_t*>(&Bsw[c][kg + 8]);
            }
#pragma unroll
            for (int ni = 0; ni < 6; ni++)
                mma_f16(acc[ni], a, b[ni]);
        }
        __syncthreads();
    }

    int row0 = bm + warp * 16 + gid;
    int row1 = row0 + 8;
#pragma unroll
    for (int ni = 0; ni < 6; ni++) {
        int col = ni * 8 + tig * 2;
        if (row0 < N_NODES)
            *reinterpret_cast<__half2*>(&g_h2h[(size_t)row0 * DP + col]) =
                __floats2half2_rn(acc[ni][0], acc[ni][1]);
        if (row1 < N_NODES)
            *reinterpret_cast<__half2*>(&g_h2h[(size_t)row1 * DP + col]) =
                __floats2half2_rn(acc[ni][2], acc[ni][3]);
    }
}

// ---------------------------------------------------------------------------
// Layer-2 gather aggregation FUSED with log-softmax.
// Block (16,16): 16 nodes per block; 16 lanes per node (12 active 4-feature
// chunks of the padded 48-wide fp16 row). Reductions via width-16 shuffles.
// ---------------------------------------------------------------------------
__global__ void __launch_bounds__(256)
k_agg2g(const float* __restrict__ b2, float* __restrict__ out) {
    int d = blockIdx.x * 16 + threadIdx.y;
    int c = threadIdx.x;          // 0..15; chunks 12..15 inactive
    float dd = g_dis[d];

    float4 acc = make_float4(-INFINITY, -INFINITY, -INFINITY, -INFINITY);
    int col = c * 4;
    if (c < 12) {
        float w = dd * dd;
        float4 bb;
        bb.x = b2[col];
        bb.y = b2[col + 1];
        bb.z = b2[col + 2];
        bb.w = (col + 3 < DOUT) ? b2[col + 3] : 0.0f;
        float2 slo, shi;
        ldh4(&g_h2h[(size_t)d * DP + col], slo, shi);
        acc = make_float4(bb.x + w * slo.x, bb.y + w * slo.y,
                          bb.z + w * shi.x, bb.w + w * shi.y);
        int i = g_off[d], end = g_off[d + 1];
        for (; i + 1 < end; i += 2) {
            int s0 = g_csr_src[i];
            int s1 = g_csr_src[i + 1];
            float n0 = g_dis[s0] * dd;
            float n1 = g_dis[s1] * dd;
            float2 a0, a1, b0, b_1;
            ldh4(&g_h2h[(size_t)s0 * DP + col], a0, a1);
            ldh4(&g_h2h[(size_t)s1 * DP + col], b0, b_1);
            acc.x += n0 * a0.x + n1 * b0.x;
            acc.y += n0 * a0.y + n1 * b0.y;
            acc.z += n0 * a1.x + n1 * b_1.x;
            acc.w += n0 * a1.y + n1 * b_1.y;
        }
        if (i < end) {
            int s = g_csr_src[i];
            float nrm = g_dis[s] * dd;
            float2 v0, v1;
            ldh4(&g_h2h[(size_t)s * DP + col], v0, v1);
            acc.x += nrm * v0.x; acc.y += nrm * v0.y;
            acc.z += nrm * v1.x; acc.w += nrm * v1.y;
        }
        if (col + 3 >= DOUT) acc.w = -INFINITY;   // pad column
    }

    // log-softmax across the 16-lane group (47 valid values).
    float m = fmaxf(fmaxf(acc.x, acc.y), fmaxf(acc.z, acc.w));
#pragma unroll
    for (int o = 8; o; o >>= 1) m = fmaxf(m, __shfl_xor_sync(0xFFFFFFFFu, m, o, 16));
    float s = __expf(acc.x - m) + __expf(acc.y - m) +
              __expf(acc.z - m) + __expf(acc.w - m);   // exp(-inf)=0
#pragma unroll
    for (int o = 8; o; o >>= 1) s += __shfl_xor_sync(0xFFFFFFFFu, s, o, 16);
    float lg = m + logf(s);

    if (c < 12) {
        float* po = &out[(size_t)d * DOUT + col];
        po[0] = acc.x - lg;
        po[1] = acc.y - lg;
        po[2] = acc.z - lg;
        if (col + 3 < DOUT) po[3] = acc.w - lg;
    }
}

// ---------------------------------------------------------------------------
extern "C" void kernel_launch(void* const* d_in, const int* in_sizes, int n_in,
                              void* d_out, int out_size) {
    const float* x  = (const float*)d_in[0];
    const int*   ew = (const int*)d_in[1];    // edge_index words (int32 view)
    const float* W1 = (const float*)d_in[2];
    const float* b1 = (const float*)d_in[3];
    const float* W2 = (const float*)d_in[4];
    const float* b2 = (const float*)d_in[5];
    float* out = (float*)d_out;
    const int E = in_sizes[1] / 2;

    k_initdet<<<(N_NODES + 255) / 256, 256>>>(ew);
    k_convX<<<(N_NODES * DIN / 8 + 255) / 256, 256>>>(x);
    k_convW<<<(DH * DIN + DP * DH + 255) / 256, 256>>>(W1, W2);
    k_extract_count<<<(E + 255) / 256, 256>>>(ew, E);
    k_scan_dis<<<1, SCAN_T>>>();
    k_fill<<<(E + 255) / 256, 256>>>(E);

    dim3 g1(DH / 128, (N_NODES + 127) / 128);
    k_gemm1h<<<g1, 256>>>();

    k_agg1g<<<N_NODES / 8, dim3(32, 8)>>>(b1);

    k_gemm2h<<<(N_NODES + 127) / 128, 256>>>();

    k_agg2g<<<N_NODES / 16, dim3(16, 16)>>>(b2, out);
}